// round 14
// baseline (speedup 1.0000x reference)
#include <cuda_runtime.h>
#include <cuda_fp16.h>
#include <cstdint>

// ---------------------------------------------------------------------------
// RelationMessagePassing (sm_103) — round 10: occupancy push.
//  - AR=3 rel kernel: 512 threads (16 warps, 4Mx4N), 128 tuples/CTA
//  - AR=2 rel kernels: 256 threads (8 warps, 2Mx4N), 64 tuples/CTA, 3 CTAs/SM
//  - update kernel: same 3-CTA structure
// fp16 2-term split mma.sync, register-direct fused exp-scatter epilogue.
//   msg = (1/8)*log(1e-16*e^{8*max} + sum exp(8*o))
// ---------------------------------------------------------------------------

#define NNODES 200000

__device__ float g_expsum[NNODES * 64];
__device__ float g_maxoff;
__device__ __half g_wh[163840];   // all weight matrices as fp16

// ------------------------------ helpers ------------------------------------
__device__ __forceinline__ uint32_t smem_u32(const void* p) {
    uint32_t a;
    asm("{ .reg .u64 t; cvta.to.shared.u64 t, %1; cvt.u32.u64 %0, t; }"
        : "=r"(a) : "l"(p));
    return a;
}

__device__ __forceinline__ void split_pair_h(float a, float b, uint32_t& hi, uint32_t& lo) {
    __half2 hp = __floats2half2_rn(a, b);
    hi = *reinterpret_cast<uint32_t*>(&hp);
    float ra = a - __half2float(__low2half(hp));
    float rb = b - __half2float(__high2half(hp));
    __half2 lp = __floats2half2_rn(ra, rb);
    lo = *reinterpret_cast<uint32_t*>(&lp);
}

__device__ __forceinline__ void ldm4(uint32_t* r, uint32_t addr) {
    asm volatile("ldmatrix.sync.aligned.m8n8.x4.shared.b16 {%0,%1,%2,%3}, [%4];"
        : "=r"(r[0]), "=r"(r[1]), "=r"(r[2]), "=r"(r[3]) : "r"(addr));
}

__device__ __forceinline__ void mma16816(float* c, const uint32_t* a, uint32_t b0, uint32_t b1) {
    asm volatile("mma.sync.aligned.m16n8k16.row.col.f32.f16.f16.f32 "
        "{%0,%1,%2,%3}, {%4,%5,%6,%7}, {%8,%9}, {%0,%1,%2,%3};"
        : "+f"(c[0]), "+f"(c[1]), "+f"(c[2]), "+f"(c[3])
        : "r"(a[0]), "r"(a[1]), "r"(a[2]), "r"(a[3]), "r"(b0), "r"(b1));
}

__device__ __forceinline__ void redv2(float* p, float a, float b) {
    asm volatile("red.global.add.v2.f32 [%0], {%1,%2};"
        :: "l"(p), "f"(a), "f"(b) : "memory");
}

__device__ __forceinline__ void atomicMaxFloat(float* addr, float v) {
    if (v >= 0.0f) atomicMax((int*)addr, __float_as_int(v));
    else           atomicMin((unsigned int*)addr, __float_as_uint(v));
}

// copy fp16 weight [NR x DK] row-major from g_wh into smem rows of pitch RS bytes
template <int THREADS>
__device__ __forceinline__ void copy_w_smem(char* sm, int off, long long wo,
                                            int NR, int DK, int RS, int tid) {
    const uint4* src = (const uint4*)(g_wh + wo);
    int n8 = DK >> 3;
    for (int e = tid; e < NR * n8; e += THREADS) {
        int r = e / n8, k8 = e - r * n8;
        *(uint4*)(sm + off + r * RS + k8 * 16) = src[e];
    }
}

// warp tile: 32(M) x NT8*8(N), K = DK; 2-term: (Ah + Al) @ Bh
// c layout: c[0..NT8*4) = m-half 0, c[NT8*4..NT8*8) = m-half 1
template <int DK, int NT8>
__device__ __forceinline__ void warp_gemm32(uint32_t xh, uint32_t xl, uint32_t wh,
                                            int RSX, int RSW,
                                            int wm, int wn, int lane, float* c) {
#pragma unroll
    for (int i = 0; i < NT8 * 8; i++) c[i] = 0.f;
    uint32_t a0 = (uint32_t)(wm * 32 + (lane & 15)) * RSX + (lane >> 4) * 16;
    uint32_t a1 = a0 + 16 * RSX;
#pragma unroll
    for (int kc = 0; kc < DK / 16; kc++) {
        uint32_t ah0[4], al0[4], ah1[4], al1[4];
        ldm4(ah0, xh + a0 + kc * 32);
        ldm4(ah1, xh + a1 + kc * 32);
        ldm4(al0, xl + a0 + kc * 32);
        ldm4(al1, xl + a1 + kc * 32);
#pragma unroll
        for (int ntp = 0; ntp < NT8 / 2; ntp++) {
            uint32_t n = (uint32_t)(wn * (NT8 * 8) + ntp * 16 + (lane & 15));
            uint32_t boff = n * RSW + kc * 32 + (lane >> 4) * 16;
            uint32_t bh[4];
            ldm4(bh, wh + boff);
            float* c00 = c + (2 * ntp) * 4;
            float* c01 = c + (2 * ntp + 1) * 4;
            float* c10 = c00 + NT8 * 4;
            float* c11 = c01 + NT8 * 4;
            mma16816(c00, ah0, bh[0], bh[2]);
            mma16816(c00, al0, bh[0], bh[2]);
            mma16816(c01, ah0, bh[1], bh[3]);
            mma16816(c01, al0, bh[1], bh[3]);
            mma16816(c10, ah1, bh[0], bh[2]);
            mma16816(c10, al1, bh[0], bh[2]);
            mma16816(c11, ah1, bh[1], bh[3]);
            mma16816(c11, al1, bh[1], bh[3]);
        }
    }
}

// ---------------------- K-1: weights fp32 -> fp16 ---------------------------
__global__ void k_w2h(const float* __restrict__ src, long long dstoff, int n) {
    int i = blockIdx.x * blockDim.x + threadIdx.x;
    if (i < n) g_wh[dstoff + i] = __float2half(src[i]);
}

// ------------------------------- K0: init -----------------------------------
__global__ void k_init() {
    long long i = (long long)blockIdx.x * blockDim.x + threadIdx.x;
    if (i == 0) g_maxoff = -3.402823466e38f;
    long long n4 = (long long)NNODES * 64 / 4;
    if (i < n4) ((float4*)g_expsum)[i] = make_float4(0.f, 0.f, 0.f, 0.f);
}

// --------------- K1..K3: relation MLP + fused exp scatter -------------------
// THREADS threads = MG*NG warps (MG m-groups x NG n-groups), warp M=32.
// Tuples per CTA = MG*32.
template <int AR, int MG, int NG, int MAXCTA>
__global__ void __launch_bounds__(MG* NG * 32, MAXCTA)
k_rel_mma(const float* __restrict__ ns, const int* __restrict__ idx,
          long long w1o, const float* __restrict__ b1,
          long long w2o, const float* __restrict__ b2, int T) {
    constexpr int THREADS = MG * NG * 32;
    constexpr int D = AR * 64;
    constexpr int NT8 = D / (8 * NG);
    constexpr int TUP = MG * 32;
    constexpr int RS = (D + 8) * 2;         // bytes per smem row (fp16, padded)
    constexpr int XSZ = TUP * RS;
    constexpr int WOFF = 2 * XSZ;
    constexpr int WSZ = D * RS;
    constexpr int BOFF = WOFF + WSZ;

    extern __shared__ char sm[];
    uint32_t sb = smem_u32(sm);
    uint32_t xh = sb, xl = sb + XSZ, wh = sb + WOFF;
    float* b1s = (float*)(sm + BOFF);
    float* b2s = b1s + D;
    float* wmax = b2s + D;

    const int tid = threadIdx.x;
    const int wid = tid >> 5, lane = tid & 31;
    const int wm = wid % MG, wn = wid / MG;
    const int t0 = blockIdx.x * TUP;

    // gather X (fp16 hi/lo) into xs
    for (int e = tid; e < TUP * AR * 16; e += THREADS) {
        int slot = e >> 4, fq = e & 15;
        int t = slot / AR, p = slot - t * AR;
        float4 v = make_float4(0.f, 0.f, 0.f, 0.f);
        if (t0 + t < T) {
            int node = idx[(t0 + t) * AR + p];
            v = *(const float4*)(ns + (long long)node * 64 + fq * 4);
        }
        uint32_t h0, l0, h1, l1;
        split_pair_h(v.x, v.y, h0, l0);
        split_pair_h(v.z, v.w, h1, l1);
        int byte = t * RS + (p * 64 + fq * 4) * 2;
        *(uint32_t*)(sm + byte) = h0;
        *(uint32_t*)(sm + byte + 4) = h1;
        *(uint32_t*)(sm + XSZ + byte) = l0;
        *(uint32_t*)(sm + XSZ + byte + 4) = l1;
    }
    copy_w_smem<THREADS>(sm, WOFF, w1o, D, D, RS, tid);
    if (tid < D) { b1s[tid] = b1[tid]; b2s[tid] = b2[tid]; }
    __syncthreads();

    float c[NT8 * 8];
    // layer 1
    warp_gemm32<D, NT8>(xh, xl, wh, RS, RS, wm, wn, lane, c);
    __syncthreads();

    // epilogue 1: bias + relu -> xs (hi/lo)
#pragma unroll
    for (int h = 0; h < 2; h++) {
#pragma unroll
        for (int nt = 0; nt < NT8; nt++) {
            int col = wn * (NT8 * 8) + nt * 8 + (lane & 3) * 2;
            float bb0 = b1s[col], bb1 = b1s[col + 1];
            int r0 = wm * 32 + h * 16 + (lane >> 2);
            const float* cc = c + h * NT8 * 4 + nt * 4;
            float v0 = fmaxf(cc[0] + bb0, 0.f), v1 = fmaxf(cc[1] + bb1, 0.f);
            float v2 = fmaxf(cc[2] + bb0, 0.f), v3 = fmaxf(cc[3] + bb1, 0.f);
            uint32_t hw, lw;
            int byte0 = r0 * RS + col * 2;
            split_pair_h(v0, v1, hw, lw);
            *(uint32_t*)(sm + byte0) = hw;
            *(uint32_t*)(sm + XSZ + byte0) = lw;
            int byte1 = (r0 + 8) * RS + col * 2;
            split_pair_h(v2, v3, hw, lw);
            *(uint32_t*)(sm + byte1) = hw;
            *(uint32_t*)(sm + XSZ + byte1) = lw;
        }
    }
    copy_w_smem<THREADS>(sm, WOFF, w2o, D, D, RS, tid);
    __syncthreads();

    // layer 2
    warp_gemm32<D, NT8>(xh, xl, wh, RS, RS, wm, wn, lane, c);

    // epilogue 2 (register-direct): bias, max, exp, red.v2 scatter
    int rbase = wm * 32 + (lane >> 2);
    int nodes[4][AR];
    bool okr[4];
#pragma unroll
    for (int s = 0; s < 4; s++) {
        int t = t0 + rbase + s * 8;
        okr[s] = t < T;
#pragma unroll
        for (int p = 0; p < AR; p++) nodes[s][p] = okr[s] ? idx[t * AR + p] : 0;
    }
    float m = -3.402823466e38f;
#pragma unroll
    for (int h = 0; h < 2; h++) {
#pragma unroll
        for (int nt = 0; nt < NT8; nt++) {
            int col = wn * (NT8 * 8) + nt * 8 + (lane & 3) * 2;
            int p = col >> 6, f = col & 63;
            float bb0 = b2s[col], bb1 = b2s[col + 1];
            const float* cc = c + h * NT8 * 4 + nt * 4;
            float v0 = cc[0] + bb0, v1 = cc[1] + bb1;
            float v2 = cc[2] + bb0, v3 = cc[3] + bb1;
            int s0 = h * 2, s1 = h * 2 + 1;
            if (okr[s0]) {
                m = fmaxf(m, fmaxf(v0, v1));
                redv2(&g_expsum[(long long)nodes[s0][p] * 64 + f],
                      __expf(8.f * v0), __expf(8.f * v1));
            }
            if (okr[s1]) {
                m = fmaxf(m, fmaxf(v2, v3));
                redv2(&g_expsum[(long long)nodes[s1][p] * 64 + f],
                      __expf(8.f * v2), __expf(8.f * v3));
            }
        }
    }
#pragma unroll
    for (int s = 16; s > 0; s >>= 1) m = fmaxf(m, __shfl_xor_sync(0xffffffffu, m, s));
    if (lane == 0) wmax[wid] = m;
    __syncthreads();
    if (tid == 0) {
        float bm = wmax[0];
#pragma unroll
        for (int w = 1; w < MG * NG; w++) bm = fmaxf(bm, wmax[w]);
        atomicMaxFloat(&g_maxoff, bm);
    }
}

// --------------------------- K4: update MLP ---------------------------------
// 64 nodes/CTA, 8 warps (2M x 4N), 3 CTAs/SM; out written register-direct.
__global__ void __launch_bounds__(256, 3)
k_update_mma(const float* __restrict__ ns,
             long long w1o, const float* __restrict__ b1,
             long long w2o, const float* __restrict__ b2,
             float* __restrict__ out) {
    constexpr int RS = (128 + 8) * 2;       // 272
    constexpr int XSZ = 64 * RS;            // 17408
    constexpr int WOFF = 2 * XSZ;           // 34816
    constexpr int WSZ = 128 * RS;           // 34816
    constexpr int BOFF = WOFF + WSZ;        // 69632

    extern __shared__ char sm[];
    uint32_t sb = smem_u32(sm);
    uint32_t xh = sb, xl = sb + XSZ, wh = sb + WOFF;
    float* b1s = (float*)(sm + BOFF);
    float* b2s = b1s + 128;

    const int tid = threadIdx.x;
    const int wid = tid >> 5, lane = tid & 31;
    const int wm = wid % 2, wn = wid / 2;
    const int n0 = blockIdx.x * 64;
    const float eps2 = 1e-16f * __expf(8.f * g_maxoff);

    // gather cat = [1/8*log(eps'+S) | ns] rows -> xs
    for (int e = tid; e < 64 * 32; e += 256) {
        int t = e >> 5, q = e & 31;
        int col = q * 4;
        long long n = n0 + t;
        if (n >= NNODES) n = NNODES - 1;    // clamp (tail rows unused)
        float4 v;
        if (col < 64) {
            float4 s = *(const float4*)(g_expsum + n * 64 + col);
            v = make_float4(0.125f * __logf(eps2 + s.x), 0.125f * __logf(eps2 + s.y),
                            0.125f * __logf(eps2 + s.z), 0.125f * __logf(eps2 + s.w));
        } else {
            v = *(const float4*)(ns + n * 64 + (col - 64));
        }
        uint32_t h0, l0, h1, l1;
        split_pair_h(v.x, v.y, h0, l0);
        split_pair_h(v.z, v.w, h1, l1);
        int byte = t * RS + col * 2;
        *(uint32_t*)(sm + byte) = h0;
        *(uint32_t*)(sm + byte + 4) = h1;
        *(uint32_t*)(sm + XSZ + byte) = l0;
        *(uint32_t*)(sm + XSZ + byte + 4) = l1;
    }
    copy_w_smem<256>(sm, WOFF, w1o, 128, 128, RS, tid);
    if (tid < 128) b1s[tid] = b1[tid];
    if (tid < 64) b2s[tid] = b2[tid];
    __syncthreads();

    float c[32];
    // layer 1: N=128, per-warp N=32 -> NT8=4
    warp_gemm32<128, 4>(xh, xl, wh, RS, RS, wm, wn, lane, c);
    __syncthreads();

#pragma unroll
    for (int h = 0; h < 2; h++) {
#pragma unroll
        for (int nt = 0; nt < 4; nt++) {
            int col = wn * 32 + nt * 8 + (lane & 3) * 2;
            float bb0 = b1s[col], bb1 = b1s[col + 1];
            int r0 = wm * 32 + h * 16 + (lane >> 2);
            const float* cc = c + h * 16 + nt * 4;
            float v0 = fmaxf(cc[0] + bb0, 0.f), v1 = fmaxf(cc[1] + bb1, 0.f);
            float v2 = fmaxf(cc[2] + bb0, 0.f), v3 = fmaxf(cc[3] + bb1, 0.f);
            uint32_t hw, lw;
            int byte0 = r0 * RS + col * 2;
            split_pair_h(v0, v1, hw, lw);
            *(uint32_t*)(sm + byte0) = hw;
            *(uint32_t*)(sm + XSZ + byte0) = lw;
            int byte1 = (r0 + 8) * RS + col * 2;
            split_pair_h(v2, v3, hw, lw);
            *(uint32_t*)(sm + byte1) = hw;
            *(uint32_t*)(sm + XSZ + byte1) = lw;
        }
    }
    copy_w_smem<256>(sm, WOFF, w2o, 64, 128, RS, tid);
    __syncthreads();

    // layer 2: N=64, per-warp N=16 -> NT8=2
    warp_gemm32<128, 2>(xh, xl, wh, RS, RS, wm, wn, lane, c);

    // epilogue 2: direct f32x2 stores
#pragma unroll
    for (int h = 0; h < 2; h++) {
#pragma unroll
        for (int nt = 0; nt < 2; nt++) {
            int col = wn * 16 + nt * 8 + (lane & 3) * 2;
            float bb0 = b2s[col], bb1 = b2s[col + 1];
            int r0 = wm * 32 + h * 16 + (lane >> 2);
            const float* cc = c + h * 8 + nt * 4;
            long long na = n0 + r0, nb = n0 + r0 + 8;
            if (na < NNODES) {
                float2 v = make_float2(cc[0] + bb0, cc[1] + bb1);
                *(float2*)(out + na * 64 + col) = v;
            }
            if (nb < NNODES) {
                float2 v = make_float2(cc[2] + bb0, cc[3] + bb1);
                *(float2*)(out + nb * 64 + col) = v;
            }
        }
    }
}

// ---------------------------------------------------------------------------
extern "C" void kernel_launch(void* const* d_in, const int* in_sizes, int n_in,
                              void* d_out, int out_size) {
    const float* ns   = (const float*)d_in[0];
    const int*   idx0 = (const int*)d_in[1];
    const int*   idx1 = (const int*)d_in[2];
    const int*   idx2 = (const int*)d_in[3];
    const float* r0w1 = (const float*)d_in[4];
    const float* r0b1 = (const float*)d_in[5];
    const float* r0w2 = (const float*)d_in[6];
    const float* r0b2 = (const float*)d_in[7];
    const float* r1w1 = (const float*)d_in[8];
    const float* r1b1 = (const float*)d_in[9];
    const float* r1w2 = (const float*)d_in[10];
    const float* r1b2 = (const float*)d_in[11];
    const float* r2w1 = (const float*)d_in[12];
    const float* r2b1 = (const float*)d_in[13];
    const float* r2w2 = (const float*)d_in[14];
    const float* r2b2 = (const float*)d_in[15];
    const float* uw1  = (const float*)d_in[16];
    const float* ub1  = (const float*)d_in[17];
    const float* uw2  = (const float*)d_in[18];
    const float* ub2  = (const float*)d_in[19];
    float* out = (float*)d_out;

    const int T01 = 300000, T2 = 200000;

    // weight offsets in g_wh (elements)
    const long long O_R0W1 = 0, O_R0W2 = 16384, O_R1W1 = 32768, O_R1W2 = 49152;
    const long long O_R2W1 = 65536, O_R2W2 = 102400, O_UW1 = 139264, O_UW2 = 155648;

    // AR=2: MG=2 NG=4 -> 64 tuples, 256 thr, 3 CTAs/SM
    const int SMA2 = 2 * (64 * 272) + 128 * 272 + 2 * 128 * 4 + 16 * 4 + 64;   // ~71KB
    // AR=3: MG=4 NG=4 -> 128 tuples, 512 thr, 1 CTA/SM
    const int SMA3 = 2 * (128 * 400) + 192 * 400 + 2 * 192 * 4 + 16 * 4 + 64;  // ~181KB
    const int SMU  = 2 * (64 * 272) + 128 * 272 + 128 * 4 + 64 * 4 + 64;       // ~70.5KB
    cudaFuncSetAttribute((const void*)k_rel_mma<2, 2, 4, 3>, cudaFuncAttributeMaxDynamicSharedMemorySize, SMA2);
    cudaFuncSetAttribute((const void*)k_rel_mma<3, 4, 4, 1>, cudaFuncAttributeMaxDynamicSharedMemorySize, SMA3);
    cudaFuncSetAttribute((const void*)k_update_mma, cudaFuncAttributeMaxDynamicSharedMemorySize, SMU);

    // K-1: precompute fp16 weights
    k_w2h<<<(16384 + 255) / 256, 256>>>(r0w1, O_R0W1, 16384);
    k_w2h<<<(16384 + 255) / 256, 256>>>(r0w2, O_R0W2, 16384);
    k_w2h<<<(16384 + 255) / 256, 256>>>(r1w1, O_R1W1, 16384);
    k_w2h<<<(16384 + 255) / 256, 256>>>(r1w2, O_R1W2, 16384);
    k_w2h<<<(36864 + 255) / 256, 256>>>(r2w1, O_R2W1, 36864);
    k_w2h<<<(36864 + 255) / 256, 256>>>(r2w2, O_R2W2, 36864);
    k_w2h<<<(16384 + 255) / 256, 256>>>(uw1,  O_UW1,  16384);
    k_w2h<<<(8192  + 255) / 256, 256>>>(uw2,  O_UW2,  8192);

    // K0
    {
        long long n4 = (long long)NNODES * 64 / 4;
        k_init<<<(int)((n4 + 255) / 256), 256>>>();
    }

    // K1..K3 (fused MLP + scatter)
    k_rel_mma<2, 2, 4, 3><<<(T01 + 63) / 64, 256, SMA2>>>(ns, idx0, O_R0W1, r0b1, O_R0W2, r0b2, T01);
    k_rel_mma<2, 2, 4, 3><<<(T01 + 63) / 64, 256, SMA2>>>(ns, idx1, O_R1W1, r1b1, O_R1W2, r1b2, T01);
    k_rel_mma<3, 4, 4, 1><<<(T2 + 127) / 128, 512, SMA3>>>(ns, idx2, O_R2W1, r2b1, O_R2W2, r2b2, T2);

    // K4
    k_update_mma<<<(NNODES + 63) / 64, 256, SMU>>>(ns, O_UW1, ub1, O_UW2, ub2, out);
}

// round 15
// speedup vs baseline: 1.2535x; 1.2535x over previous
#include <cuda_runtime.h>
#include <cuda_fp16.h>
#include <cstdint>

// ---------------------------------------------------------------------------
// RelationMessagePassing (sm_103) — round 11: R9 config (best) +
//  (a) single fused weight fp32->fp16 conversion kernel (kills 8 launches)
//  (b) shfl-paired red.global.add.v4 scatter (halves atomic op count)
// fp16 2-term split mma.sync, warp M=32, register-direct fused epilogue.
//   msg = (1/8)*log(1e-16*e^{8*max} + sum exp(8*o))
// ---------------------------------------------------------------------------

#define NNODES 200000

__device__ float g_expsum[NNODES * 64];
__device__ float g_maxoff;
__device__ __half g_wh[163840];   // all weight matrices as fp16

// ------------------------------ helpers ------------------------------------
__device__ __forceinline__ uint32_t smem_u32(const void* p) {
    uint32_t a;
    asm("{ .reg .u64 t; cvta.to.shared.u64 t, %1; cvt.u32.u64 %0, t; }"
        : "=r"(a) : "l"(p));
    return a;
}

__device__ __forceinline__ void split_pair_h(float a, float b, uint32_t& hi, uint32_t& lo) {
    __half2 hp = __floats2half2_rn(a, b);
    hi = *reinterpret_cast<uint32_t*>(&hp);
    float ra = a - __half2float(__low2half(hp));
    float rb = b - __half2float(__high2half(hp));
    __half2 lp = __floats2half2_rn(ra, rb);
    lo = *reinterpret_cast<uint32_t*>(&lp);
}

__device__ __forceinline__ void ldm4(uint32_t* r, uint32_t addr) {
    asm volatile("ldmatrix.sync.aligned.m8n8.x4.shared.b16 {%0,%1,%2,%3}, [%4];"
        : "=r"(r[0]), "=r"(r[1]), "=r"(r[2]), "=r"(r[3]) : "r"(addr));
}

__device__ __forceinline__ void mma16816(float* c, const uint32_t* a, uint32_t b0, uint32_t b1) {
    asm volatile("mma.sync.aligned.m16n8k16.row.col.f32.f16.f16.f32 "
        "{%0,%1,%2,%3}, {%4,%5,%6,%7}, {%8,%9}, {%0,%1,%2,%3};"
        : "+f"(c[0]), "+f"(c[1]), "+f"(c[2]), "+f"(c[3])
        : "r"(a[0]), "r"(a[1]), "r"(a[2]), "r"(a[3]), "r"(b0), "r"(b1));
}

__device__ __forceinline__ void redv4(float* p, float a, float b, float c, float d) {
    asm volatile("red.global.add.v4.f32 [%0], {%1,%2,%3,%4};"
        :: "l"(p), "f"(a), "f"(b), "f"(c), "f"(d) : "memory");
}

__device__ __forceinline__ void atomicMaxFloat(float* addr, float v) {
    if (v >= 0.0f) atomicMax((int*)addr, __float_as_int(v));
    else           atomicMin((unsigned int*)addr, __float_as_uint(v));
}

// copy fp16 weight [NR x DK] row-major from g_wh into smem rows of pitch RS bytes
__device__ __forceinline__ void copy_w_smem(char* sm, int off, long long wo,
                                            int NR, int DK, int RS, int tid) {
    const uint4* src = (const uint4*)(g_wh + wo);
    int n8 = DK >> 3;
    for (int e = tid; e < NR * n8; e += 256) {
        int r = e / n8, k8 = e - r * n8;
        *(uint4*)(sm + off + r * RS + k8 * 16) = src[e];
    }
}

// warp tile: 32(M) x NT8*8(N), K = DK; 2-term: (Ah + Al) @ Bh
// c layout: c[0..NT8*4) = m-half 0, c[NT8*4..NT8*8) = m-half 1
template <int DK, int NT8>
__device__ __forceinline__ void warp_gemm32(uint32_t xh, uint32_t xl, uint32_t wh,
                                            int RSX, int RSW,
                                            int wm, int wn, int lane, float* c) {
#pragma unroll
    for (int i = 0; i < NT8 * 8; i++) c[i] = 0.f;
    uint32_t a0 = (uint32_t)(wm * 32 + (lane & 15)) * RSX + (lane >> 4) * 16;
    uint32_t a1 = a0 + 16 * RSX;
#pragma unroll
    for (int kc = 0; kc < DK / 16; kc++) {
        uint32_t ah0[4], al0[4], ah1[4], al1[4];
        ldm4(ah0, xh + a0 + kc * 32);
        ldm4(ah1, xh + a1 + kc * 32);
        ldm4(al0, xl + a0 + kc * 32);
        ldm4(al1, xl + a1 + kc * 32);
#pragma unroll
        for (int ntp = 0; ntp < NT8 / 2; ntp++) {
            uint32_t n = (uint32_t)(wn * (NT8 * 8) + ntp * 16 + (lane & 15));
            uint32_t boff = n * RSW + kc * 32 + (lane >> 4) * 16;
            uint32_t bh[4];
            ldm4(bh, wh + boff);
            float* c00 = c + (2 * ntp) * 4;
            float* c01 = c + (2 * ntp + 1) * 4;
            float* c10 = c00 + NT8 * 4;
            float* c11 = c01 + NT8 * 4;
            mma16816(c00, ah0, bh[0], bh[2]);
            mma16816(c00, al0, bh[0], bh[2]);
            mma16816(c01, ah0, bh[1], bh[3]);
            mma16816(c01, al0, bh[1], bh[3]);
            mma16816(c10, ah1, bh[0], bh[2]);
            mma16816(c10, al1, bh[0], bh[2]);
            mma16816(c11, ah1, bh[1], bh[3]);
            mma16816(c11, al1, bh[1], bh[3]);
        }
    }
}

// ---------------- K-1: ALL weights fp32 -> fp16 in ONE launch ----------------
__global__ void k_wprep(const float* w0, const float* w1, const float* w2,
                        const float* w3, const float* w4, const float* w5,
                        const float* w6, const float* w7) {
    int i = blockIdx.x * blockDim.x + threadIdx.x;   // 0..163839
    const float* src;
    int off;
    if      (i < 16384)  { src = w0; off = 0;      }
    else if (i < 32768)  { src = w1; off = 16384;  }
    else if (i < 49152)  { src = w2; off = 32768;  }
    else if (i < 65536)  { src = w3; off = 49152;  }
    else if (i < 102400) { src = w4; off = 65536;  }
    else if (i < 139264) { src = w5; off = 102400; }
    else if (i < 155648) { src = w6; off = 139264; }
    else                 { src = w7; off = 155648; }
    g_wh[i] = __float2half(src[i - off]);
}

// ------------------------------- K0: init -----------------------------------
__global__ void k_init() {
    long long i = (long long)blockIdx.x * blockDim.x + threadIdx.x;
    if (i == 0) g_maxoff = -3.402823466e38f;
    long long n4 = (long long)NNODES * 64 / 4;
    if (i < n4) ((float4*)g_expsum)[i] = make_float4(0.f, 0.f, 0.f, 0.f);
}

// --------------- K1..K3: relation MLP + fused exp scatter -------------------
// 256 threads = 8 warps (4 M x 2 N), warp M=32 -> 128 tuples/CTA.
template <int AR, int MAXCTA>
__global__ void __launch_bounds__(256, MAXCTA)
k_rel_mma(const float* __restrict__ ns, const int* __restrict__ idx,
          long long w1o, const float* __restrict__ b1,
          long long w2o, const float* __restrict__ b2, int T) {
    constexpr int D = AR * 64;
    constexpr int ND2 = D / 2;
    constexpr int NT8 = ND2 / 8;
    constexpr int RS = (D + 8) * 2;         // bytes per smem row (fp16, padded)
    constexpr int XSZ = 128 * RS;
    constexpr int WOFF = 2 * XSZ;
    constexpr int WSZ = D * RS;
    constexpr int BOFF = WOFF + WSZ;

    extern __shared__ char sm[];
    uint32_t sb = smem_u32(sm);
    uint32_t xh = sb, xl = sb + XSZ, wh = sb + WOFF;
    float* b1s = (float*)(sm + BOFF);
    float* b2s = b1s + D;
    float* wmax = b2s + D;

    const int tid = threadIdx.x;
    const int wid = tid >> 5, lane = tid & 31;
    const int wm = wid >> 1, wn = wid & 1;
    const int t0 = blockIdx.x * 128;

    // gather X (fp16 hi/lo) into xs
    for (int e = tid; e < 128 * AR * 16; e += 256) {
        int slot = e >> 4, fq = e & 15;
        int t = slot / AR, p = slot - t * AR;
        float4 v = make_float4(0.f, 0.f, 0.f, 0.f);
        if (t0 + t < T) {
            int node = idx[(t0 + t) * AR + p];
            v = *(const float4*)(ns + (long long)node * 64 + fq * 4);
        }
        uint32_t h0, l0, h1, l1;
        split_pair_h(v.x, v.y, h0, l0);
        split_pair_h(v.z, v.w, h1, l1);
        int byte = t * RS + (p * 64 + fq * 4) * 2;
        *(uint32_t*)(sm + byte) = h0;
        *(uint32_t*)(sm + byte + 4) = h1;
        *(uint32_t*)(sm + XSZ + byte) = l0;
        *(uint32_t*)(sm + XSZ + byte + 4) = l1;
    }
    copy_w_smem(sm, WOFF, w1o, D, D, RS, tid);
    if (tid < D) { b1s[tid] = b1[tid]; b2s[tid] = b2[tid]; }
    __syncthreads();

    float c[NT8 * 8];
    // layer 1
    warp_gemm32<D, NT8>(xh, xl, wh, RS, RS, wm, wn, lane, c);
    __syncthreads();

    // epilogue 1: bias + relu -> xs (hi/lo)
#pragma unroll
    for (int h = 0; h < 2; h++) {
#pragma unroll
        for (int nt = 0; nt < NT8; nt++) {
            int col = wn * ND2 + nt * 8 + (lane & 3) * 2;
            float bb0 = b1s[col], bb1 = b1s[col + 1];
            int r0 = wm * 32 + h * 16 + (lane >> 2);
            const float* cc = c + h * NT8 * 4 + nt * 4;
            float v0 = fmaxf(cc[0] + bb0, 0.f), v1 = fmaxf(cc[1] + bb1, 0.f);
            float v2 = fmaxf(cc[2] + bb0, 0.f), v3 = fmaxf(cc[3] + bb1, 0.f);
            uint32_t hw, lw;
            int byte0 = r0 * RS + col * 2;
            split_pair_h(v0, v1, hw, lw);
            *(uint32_t*)(sm + byte0) = hw;
            *(uint32_t*)(sm + XSZ + byte0) = lw;
            int byte1 = (r0 + 8) * RS + col * 2;
            split_pair_h(v2, v3, hw, lw);
            *(uint32_t*)(sm + byte1) = hw;
            *(uint32_t*)(sm + XSZ + byte1) = lw;
        }
    }
    copy_w_smem(sm, WOFF, w2o, D, D, RS, tid);
    __syncthreads();

    // layer 2
    warp_gemm32<D, NT8>(xh, xl, wh, RS, RS, wm, wn, lane, c);

    // epilogue 2 (register-direct): bias, max, exp, shfl-paired red.v4 scatter
    int rbase = wm * 32 + (lane >> 2);
    int nodes[4][AR];
    bool okr[4];
#pragma unroll
    for (int s = 0; s < 4; s++) {
        int t = t0 + rbase + s * 8;
        okr[s] = t < T;
#pragma unroll
        for (int p = 0; p < AR; p++) nodes[s][p] = okr[s] ? idx[t * AR + p] : 0;
    }
    float m = -3.402823466e38f;
    const bool evlane = (lane & 1) == 0;
#pragma unroll
    for (int h = 0; h < 2; h++) {
#pragma unroll
        for (int nt = 0; nt < NT8; nt++) {
            int col = wn * ND2 + nt * 8 + (lane & 3) * 2;
            int p = col >> 6, f = col & 63;
            float bb0 = b2s[col], bb1 = b2s[col + 1];
            const float* cc = c + h * NT8 * 4 + nt * 4;
            float v0 = cc[0] + bb0, v1 = cc[1] + bb1;
            float v2 = cc[2] + bb0, v3 = cc[3] + bb1;
            int s0 = h * 2, s1 = h * 2 + 1;
            // exps computed by ALL lanes (shfl validity); invalid rows gated below
            float e0 = __expf(8.f * v0), e1 = __expf(8.f * v1);
            float e2 = __expf(8.f * v2), e3 = __expf(8.f * v3);
            float pe0 = __shfl_xor_sync(0xffffffffu, e0, 1);
            float pe1 = __shfl_xor_sync(0xffffffffu, e1, 1);
            float pe2 = __shfl_xor_sync(0xffffffffu, e2, 1);
            float pe3 = __shfl_xor_sync(0xffffffffu, e3, 1);
            if (okr[s0]) m = fmaxf(m, fmaxf(v0, v1));
            if (okr[s1]) m = fmaxf(m, fmaxf(v2, v3));
            if (evlane) {
                // even lane owns cols f..f+1, partner owns f+2..f+3 (same node)
                if (okr[s0])
                    redv4(&g_expsum[(long long)nodes[s0][p] * 64 + f], e0, e1, pe0, pe1);
                if (okr[s1])
                    redv4(&g_expsum[(long long)nodes[s1][p] * 64 + f], e2, e3, pe2, pe3);
            }
        }
    }
#pragma unroll
    for (int s = 16; s > 0; s >>= 1) m = fmaxf(m, __shfl_xor_sync(0xffffffffu, m, s));
    if (lane == 0) wmax[wid] = m;
    __syncthreads();
    if (tid == 0) {
        float bm = wmax[0];
#pragma unroll
        for (int w = 1; w < 8; w++) bm = fmaxf(bm, wmax[w]);
        atomicMaxFloat(&g_maxoff, bm);
    }
}

// --------------------------- K4: update MLP ---------------------------------
// 128 nodes/CTA, warp M=32; out written register-direct.
__global__ void __launch_bounds__(256, 2)
k_update_mma(const float* __restrict__ ns,
             long long w1o, const float* __restrict__ b1,
             long long w2o, const float* __restrict__ b2,
             float* __restrict__ out) {
    constexpr int RS = (128 + 8) * 2;       // 272
    constexpr int XSZ = 128 * RS;           // 34816
    constexpr int WOFF = 2 * XSZ;           // 69632
    constexpr int WSZ = 128 * RS;           // 34816
    constexpr int BOFF = WOFF + WSZ;        // 104448

    extern __shared__ char sm[];
    uint32_t sb = smem_u32(sm);
    uint32_t xh = sb, xl = sb + XSZ, wh = sb + WOFF;
    float* b1s = (float*)(sm + BOFF);
    float* b2s = b1s + 128;

    const int tid = threadIdx.x;
    const int wid = tid >> 5, lane = tid & 31;
    const int wm = wid >> 1, wn = wid & 1;
    const int n0 = blockIdx.x * 128;
    const float eps2 = 1e-16f * __expf(8.f * g_maxoff);

    // gather cat = [1/8*log(eps'+S) | ns] rows -> xs
    for (int e = tid; e < 128 * 32; e += 256) {
        int t = e >> 5, q = e & 31;
        int col = q * 4;
        long long n = n0 + t;
        if (n >= NNODES) n = NNODES - 1;    // clamp (tail rows unused)
        float4 v;
        if (col < 64) {
            float4 s = *(const float4*)(g_expsum + n * 64 + col);
            v = make_float4(0.125f * __logf(eps2 + s.x), 0.125f * __logf(eps2 + s.y),
                            0.125f * __logf(eps2 + s.z), 0.125f * __logf(eps2 + s.w));
        } else {
            v = *(const float4*)(ns + n * 64 + (col - 64));
        }
        uint32_t h0, l0, h1, l1;
        split_pair_h(v.x, v.y, h0, l0);
        split_pair_h(v.z, v.w, h1, l1);
        int byte = t * RS + col * 2;
        *(uint32_t*)(sm + byte) = h0;
        *(uint32_t*)(sm + byte + 4) = h1;
        *(uint32_t*)(sm + XSZ + byte) = l0;
        *(uint32_t*)(sm + XSZ + byte + 4) = l1;
    }
    copy_w_smem(sm, WOFF, w1o, 128, 128, RS, tid);
    if (tid < 128) b1s[tid] = b1[tid];
    if (tid < 64) b2s[tid] = b2[tid];
    __syncthreads();

    float c[64];
    // layer 1: N=128, warp half = 64 -> NT8=8
    warp_gemm32<128, 8>(xh, xl, wh, RS, RS, wm, wn, lane, c);
    __syncthreads();

#pragma unroll
    for (int h = 0; h < 2; h++) {
#pragma unroll
        for (int nt = 0; nt < 8; nt++) {
            int col = wn * 64 + nt * 8 + (lane & 3) * 2;
            float bb0 = b1s[col], bb1 = b1s[col + 1];
            int r0 = wm * 32 + h * 16 + (lane >> 2);
            const float* cc = c + h * 32 + nt * 4;
            float v0 = fmaxf(cc[0] + bb0, 0.f), v1 = fmaxf(cc[1] + bb1, 0.f);
            float v2 = fmaxf(cc[2] + bb0, 0.f), v3 = fmaxf(cc[3] + bb1, 0.f);
            uint32_t hw, lw;
            int byte0 = r0 * RS + col * 2;
            split_pair_h(v0, v1, hw, lw);
            *(uint32_t*)(sm + byte0) = hw;
            *(uint32_t*)(sm + XSZ + byte0) = lw;
            int byte1 = (r0 + 8) * RS + col * 2;
            split_pair_h(v2, v3, hw, lw);
            *(uint32_t*)(sm + byte1) = hw;
            *(uint32_t*)(sm + XSZ + byte1) = lw;
        }
    }
    copy_w_smem(sm, WOFF, w2o, 64, 128, RS, tid);
    __syncthreads();

    // layer 2: N=64, warp half = 32 -> NT8=4
    warp_gemm32<128, 4>(xh, xl, wh, RS, RS, wm, wn, lane, c);

    // epilogue 2: direct f32x2 stores
#pragma unroll
    for (int h = 0; h < 2; h++) {
#pragma unroll
        for (int nt = 0; nt < 4; nt++) {
            int col = wn * 32 + nt * 8 + (lane & 3) * 2;
            float bb0 = b2s[col], bb1 = b2s[col + 1];
            int r0 = wm * 32 + h * 16 + (lane >> 2);
            const float* cc = c + h * 16 + nt * 4;
            long long na = n0 + r0, nb = n0 + r0 + 8;
            if (na < NNODES) {
                float2 v = make_float2(cc[0] + bb0, cc[1] + bb1);
                *(float2*)(out + na * 64 + col) = v;
            }
            if (nb < NNODES) {
                float2 v = make_float2(cc[2] + bb0, cc[3] + bb1);
                *(float2*)(out + nb * 64 + col) = v;
            }
        }
    }
}

// ---------------------------------------------------------------------------
extern "C" void kernel_launch(void* const* d_in, const int* in_sizes, int n_in,
                              void* d_out, int out_size) {
    const float* ns   = (const float*)d_in[0];
    const int*   idx0 = (const int*)d_in[1];
    const int*   idx1 = (const int*)d_in[2];
    const int*   idx2 = (const int*)d_in[3];
    const float* r0w1 = (const float*)d_in[4];
    const float* r0b1 = (const float*)d_in[5];
    const float* r0w2 = (const float*)d_in[6];
    const float* r0b2 = (const float*)d_in[7];
    const float* r1w1 = (const float*)d_in[8];
    const float* r1b1 = (const float*)d_in[9];
    const float* r1w2 = (const float*)d_in[10];
    const float* r1b2 = (const float*)d_in[11];
    const float* r2w1 = (const float*)d_in[12];
    const float* r2b1 = (const float*)d_in[13];
    const float* r2w2 = (const float*)d_in[14];
    const float* r2b2 = (const float*)d_in[15];
    const float* uw1  = (const float*)d_in[16];
    const float* ub1  = (const float*)d_in[17];
    const float* uw2  = (const float*)d_in[18];
    const float* ub2  = (const float*)d_in[19];
    float* out = (float*)d_out;

    const int T01 = 300000, T2 = 200000;

    // weight offsets in g_wh (elements)
    const long long O_R0W1 = 0, O_R0W2 = 16384, O_R1W1 = 32768, O_R1W2 = 49152;
    const long long O_R2W1 = 65536, O_R2W2 = 102400, O_UW1 = 139264, O_UW2 = 155648;

    const int SMA2 = 2 * (128 * 272) + 128 * 272 + 2 * 128 * 4 + 64;   // 105.5KB
    const int SMA3 = 2 * (128 * 400) + 192 * 400 + 2 * 192 * 4 + 64;   // 180.8KB
    const int SMU  = 2 * (128 * 272) + 128 * 272 + 128 * 4 + 64 * 4 + 64;
    cudaFuncSetAttribute((const void*)k_rel_mma<2, 2>, cudaFuncAttributeMaxDynamicSharedMemorySize, SMA2);
    cudaFuncSetAttribute((const void*)k_rel_mma<3, 1>, cudaFuncAttributeMaxDynamicSharedMemorySize, SMA3);
    cudaFuncSetAttribute((const void*)k_update_mma, cudaFuncAttributeMaxDynamicSharedMemorySize, SMU);

    // K-1: all weights -> fp16 in one launch (163840 elements)
    k_wprep<<<163840 / 256, 256>>>(r0w1, r0w2, r1w1, r1w2, r2w1, r2w2, uw1, uw2);

    // K0
    {
        long long n4 = (long long)NNODES * 64 / 4;
        k_init<<<(int)((n4 + 255) / 256), 256>>>();
    }

    // K1..K3 (fused MLP + scatter)
    k_rel_mma<2, 2><<<(T01 + 127) / 128, 256, SMA2>>>(ns, idx0, O_R0W1, r0b1, O_R0W2, r0b2, T01);
    k_rel_mma<2, 2><<<(T01 + 127) / 128, 256, SMA2>>>(ns, idx1, O_R1W1, r1b1, O_R1W2, r1b2, T01);
    k_rel_mma<3, 1><<<(T2 + 127) / 128, 256, SMA3>>>(ns, idx2, O_R2W1, r2b1, O_R2W2, r2b2, T2);

    // K4
    k_update_mma<<<(NNODES + 127) / 128, 256, SMU>>>(ns, O_UW1, ub1, O_UW2, ub2, out);
}

// round 17
// speedup vs baseline: 1.3224x; 1.0550x over previous
#include <cuda_runtime.h>
#include <cuda_fp16.h>
#include <cstdint>

// ---------------------------------------------------------------------------
// RelationMessagePassing (sm_103) — round 12: R9 config (best) +
//  (a) fused prep kernel: expsum init + weights fp32->fp16 + node_states
//      pre-split to fp16 hi/lo (gathers become pure uint4 copies)
//  (b) plain red.global.add.v2 scatter (R9 proven; shfl-pairing reverted)
// fp16 2-term split mma.sync, warp M=32, register-direct fused epilogue.
//   msg = (1/8)*log(1e-16*e^{8*max} + sum exp(8*o))
// ---------------------------------------------------------------------------

#define NNODES 200000

__device__ float g_expsum[NNODES * 64];
__device__ float g_maxoff;
__device__ __half g_wh[163840];           // all weight matrices as fp16
__device__ __half g_nsh_hi[NNODES * 64];  // node_states fp16 hi
__device__ __half g_nsh_lo[NNODES * 64];  // node_states fp16 residual

// ------------------------------ helpers ------------------------------------
__device__ __forceinline__ uint32_t smem_u32(const void* p) {
    uint32_t a;
    asm("{ .reg .u64 t; cvta.to.shared.u64 t, %1; cvt.u32.u64 %0, t; }"
        : "=r"(a) : "l"(p));
    return a;
}

__device__ __forceinline__ void split_pair_h(float a, float b, uint32_t& hi, uint32_t& lo) {
    __half2 hp = __floats2half2_rn(a, b);
    hi = *reinterpret_cast<uint32_t*>(&hp);
    float ra = a - __half2float(__low2half(hp));
    float rb = b - __half2float(__high2half(hp));
    __half2 lp = __floats2half2_rn(ra, rb);
    lo = *reinterpret_cast<uint32_t*>(&lp);
}

__device__ __forceinline__ void ldm4(uint32_t* r, uint32_t addr) {
    asm volatile("ldmatrix.sync.aligned.m8n8.x4.shared.b16 {%0,%1,%2,%3}, [%4];"
        : "=r"(r[0]), "=r"(r[1]), "=r"(r[2]), "=r"(r[3]) : "r"(addr));
}

__device__ __forceinline__ void mma16816(float* c, const uint32_t* a, uint32_t b0, uint32_t b1) {
    asm volatile("mma.sync.aligned.m16n8k16.row.col.f32.f16.f16.f32 "
        "{%0,%1,%2,%3}, {%4,%5,%6,%7}, {%8,%9}, {%0,%1,%2,%3};"
        : "+f"(c[0]), "+f"(c[1]), "+f"(c[2]), "+f"(c[3])
        : "r"(a[0]), "r"(a[1]), "r"(a[2]), "r"(a[3]), "r"(b0), "r"(b1));
}

__device__ __forceinline__ void redv2(float* p, float a, float b) {
    asm volatile("red.global.add.v2.f32 [%0], {%1,%2};"
        :: "l"(p), "f"(a), "f"(b) : "memory");
}

__device__ __forceinline__ void atomicMaxFloat(float* addr, float v) {
    if (v >= 0.0f) atomicMax((int*)addr, __float_as_int(v));
    else           atomicMin((unsigned int*)addr, __float_as_uint(v));
}

// copy fp16 weight [NR x DK] row-major from g_wh into smem rows of pitch RS bytes
__device__ __forceinline__ void copy_w_smem(char* sm, int off, long long wo,
                                            int NR, int DK, int RS, int tid) {
    const uint4* src = (const uint4*)(g_wh + wo);
    int n8 = DK >> 3;
    for (int e = tid; e < NR * n8; e += 256) {
        int r = e / n8, k8 = e - r * n8;
        *(uint4*)(sm + off + r * RS + k8 * 16) = src[e];
    }
}

// warp tile: 32(M) x NT8*8(N), K = DK; 2-term: (Ah + Al) @ Bh
// c layout: c[0..NT8*4) = m-half 0, c[NT8*4..NT8*8) = m-half 1
template <int DK, int NT8>
__device__ __forceinline__ void warp_gemm32(uint32_t xh, uint32_t xl, uint32_t wh,
                                            int RSX, int RSW,
                                            int wm, int wn, int lane, float* c) {
#pragma unroll
    for (int i = 0; i < NT8 * 8; i++) c[i] = 0.f;
    uint32_t a0 = (uint32_t)(wm * 32 + (lane & 15)) * RSX + (lane >> 4) * 16;
    uint32_t a1 = a0 + 16 * RSX;
#pragma unroll
    for (int kc = 0; kc < DK / 16; kc++) {
        uint32_t ah0[4], al0[4], ah1[4], al1[4];
        ldm4(ah0, xh + a0 + kc * 32);
        ldm4(ah1, xh + a1 + kc * 32);
        ldm4(al0, xl + a0 + kc * 32);
        ldm4(al1, xl + a1 + kc * 32);
#pragma unroll
        for (int ntp = 0; ntp < NT8 / 2; ntp++) {
            uint32_t n = (uint32_t)(wn * (NT8 * 8) + ntp * 16 + (lane & 15));
            uint32_t boff = n * RSW + kc * 32 + (lane >> 4) * 16;
            uint32_t bh[4];
            ldm4(bh, wh + boff);
            float* c00 = c + (2 * ntp) * 4;
            float* c01 = c + (2 * ntp + 1) * 4;
            float* c10 = c00 + NT8 * 4;
            float* c11 = c01 + NT8 * 4;
            mma16816(c00, ah0, bh[0], bh[2]);
            mma16816(c00, al0, bh[0], bh[2]);
            mma16816(c01, ah0, bh[1], bh[3]);
            mma16816(c01, al0, bh[1], bh[3]);
            mma16816(c10, ah1, bh[0], bh[2]);
            mma16816(c10, al1, bh[0], bh[2]);
            mma16816(c11, ah1, bh[1], bh[3]);
            mma16816(c11, al1, bh[1], bh[3]);
        }
    }
}

// ---- K0: fused prep: expsum init + node_states hi/lo split + weights fp16 ----
__global__ void k_prep(const float* __restrict__ ns,
                       const float* w0, const float* w1, const float* w2,
                       const float* w3, const float* w4, const float* w5,
                       const float* w6, const float* w7) {
    int i = blockIdx.x * blockDim.x + threadIdx.x;
    if (i == 0) g_maxoff = -3.402823466e38f;
    long long n4 = (long long)NNODES * 64 / 4;   // 3.2M float4 groups
    if (i < n4) {
        ((float4*)g_expsum)[i] = make_float4(0.f, 0.f, 0.f, 0.f);
        float4 v = ((const float4*)ns)[i];
        uint32_t h0, l0, h1, l1;
        split_pair_h(v.x, v.y, h0, l0);
        split_pair_h(v.z, v.w, h1, l1);
        ((uint2*)g_nsh_hi)[i] = make_uint2(h0, h1);
        ((uint2*)g_nsh_lo)[i] = make_uint2(l0, l1);
    }
    if (i < 163840) {
        const float* src;
        int off;
        if      (i < 16384)  { src = w0; off = 0;      }
        else if (i < 32768)  { src = w1; off = 16384;  }
        else if (i < 49152)  { src = w2; off = 32768;  }
        else if (i < 65536)  { src = w3; off = 49152;  }
        else if (i < 102400) { src = w4; off = 65536;  }
        else if (i < 139264) { src = w5; off = 102400; }
        else if (i < 155648) { src = w6; off = 139264; }
        else                 { src = w7; off = 155648; }
        g_wh[i] = __float2half(src[i - off]);
    }
}

// --------------- K1..K3: relation MLP + fused exp scatter -------------------
// 256 threads = 8 warps (4 M x 2 N), warp M=32 -> 128 tuples/CTA.
template <int AR, int MAXCTA>
__global__ void __launch_bounds__(256, MAXCTA)
k_rel_mma(const int* __restrict__ idx,
          long long w1o, const float* __restrict__ b1,
          long long w2o, const float* __restrict__ b2, int T) {
    constexpr int D = AR * 64;
    constexpr int ND2 = D / 2;
    constexpr int NT8 = ND2 / 8;
    constexpr int RS = (D + 8) * 2;         // bytes per smem row (fp16, padded)
    constexpr int XSZ = 128 * RS;
    constexpr int WOFF = 2 * XSZ;
    constexpr int WSZ = D * RS;
    constexpr int BOFF = WOFF + WSZ;

    extern __shared__ char sm[];
    uint32_t sb = smem_u32(sm);
    uint32_t xh = sb, xl = sb + XSZ, wh = sb + WOFF;
    float* b1s = (float*)(sm + BOFF);
    float* b2s = b1s + D;
    float* wmax = b2s + D;

    const int tid = threadIdx.x;
    const int wid = tid >> 5, lane = tid & 31;
    const int wm = wid >> 1, wn = wid & 1;
    const int t0 = blockIdx.x * 128;

    // gather X: pure uint4 copies from pre-split fp16 hi/lo node states
    for (int e = tid; e < 128 * AR * 8; e += 256) {
        int slot = e >> 3, fq = e & 7;
        int t = slot / AR, p = slot - t * AR;
        uint4 hv = make_uint4(0, 0, 0, 0), lv = make_uint4(0, 0, 0, 0);
        if (t0 + t < T) {
            int node = idx[(t0 + t) * AR + p];
            long long base = (long long)node * 64 + fq * 8;
            hv = *(const uint4*)(g_nsh_hi + base);
            lv = *(const uint4*)(g_nsh_lo + base);
        }
        int byte = t * RS + (p * 64 + fq * 8) * 2;
        *(uint4*)(sm + byte) = hv;
        *(uint4*)(sm + XSZ + byte) = lv;
    }
    copy_w_smem(sm, WOFF, w1o, D, D, RS, tid);
    if (tid < D) { b1s[tid] = b1[tid]; b2s[tid] = b2[tid]; }
    __syncthreads();

    float c[NT8 * 8];
    // layer 1
    warp_gemm32<D, NT8>(xh, xl, wh, RS, RS, wm, wn, lane, c);
    __syncthreads();

    // epilogue 1: bias + relu -> xs (hi/lo)
#pragma unroll
    for (int h = 0; h < 2; h++) {
#pragma unroll
        for (int nt = 0; nt < NT8; nt++) {
            int col = wn * ND2 + nt * 8 + (lane & 3) * 2;
            float bb0 = b1s[col], bb1 = b1s[col + 1];
            int r0 = wm * 32 + h * 16 + (lane >> 2);
            const float* cc = c + h * NT8 * 4 + nt * 4;
            float v0 = fmaxf(cc[0] + bb0, 0.f), v1 = fmaxf(cc[1] + bb1, 0.f);
            float v2 = fmaxf(cc[2] + bb0, 0.f), v3 = fmaxf(cc[3] + bb1, 0.f);
            uint32_t hw, lw;
            int byte0 = r0 * RS + col * 2;
            split_pair_h(v0, v1, hw, lw);
            *(uint32_t*)(sm + byte0) = hw;
            *(uint32_t*)(sm + XSZ + byte0) = lw;
            int byte1 = (r0 + 8) * RS + col * 2;
            split_pair_h(v2, v3, hw, lw);
            *(uint32_t*)(sm + byte1) = hw;
            *(uint32_t*)(sm + XSZ + byte1) = lw;
        }
    }
    copy_w_smem(sm, WOFF, w2o, D, D, RS, tid);
    __syncthreads();

    // layer 2
    warp_gemm32<D, NT8>(xh, xl, wh, RS, RS, wm, wn, lane, c);

    // epilogue 2 (register-direct): bias, max, exp, red.v2 scatter
    int rbase = wm * 32 + (lane >> 2);
    int nodes[4][AR];
    bool okr[4];
#pragma unroll
    for (int s = 0; s < 4; s++) {
        int t = t0 + rbase + s * 8;
        okr[s] = t < T;
#pragma unroll
        for (int p = 0; p < AR; p++) nodes[s][p] = okr[s] ? idx[t * AR + p] : 0;
    }
    float m = -3.402823466e38f;
#pragma unroll
    for (int h = 0; h < 2; h++) {
#pragma unroll
        for (int nt = 0; nt < NT8; nt++) {
            int col = wn * ND2 + nt * 8 + (lane & 3) * 2;
            int p = col >> 6, f = col & 63;
            float bb0 = b2s[col], bb1 = b2s[col + 1];
            const float* cc = c + h * NT8 * 4 + nt * 4;
            float v0 = cc[0] + bb0, v1 = cc[1] + bb1;
            float v2 = cc[2] + bb0, v3 = cc[3] + bb1;
            int s0 = h * 2, s1 = h * 2 + 1;
            if (okr[s0]) {
                m = fmaxf(m, fmaxf(v0, v1));
                redv2(&g_expsum[(long long)nodes[s0][p] * 64 + f],
                      __expf(8.f * v0), __expf(8.f * v1));
            }
            if (okr[s1]) {
                m = fmaxf(m, fmaxf(v2, v3));
                redv2(&g_expsum[(long long)nodes[s1][p] * 64 + f],
                      __expf(8.f * v2), __expf(8.f * v3));
            }
        }
    }
#pragma unroll
    for (int s = 16; s > 0; s >>= 1) m = fmaxf(m, __shfl_xor_sync(0xffffffffu, m, s));
    if (lane == 0) wmax[wid] = m;
    __syncthreads();
    if (tid == 0) {
        float bm = wmax[0];
#pragma unroll
        for (int w = 1; w < 8; w++) bm = fmaxf(bm, wmax[w]);
        atomicMaxFloat(&g_maxoff, bm);
    }
}

// --------------------------- K4: update MLP ---------------------------------
// 128 nodes/CTA, warp M=32; out written register-direct.
__global__ void __launch_bounds__(256, 2)
k_update_mma(long long w1o, const float* __restrict__ b1,
             long long w2o, const float* __restrict__ b2,
             float* __restrict__ out) {
    constexpr int RS = (128 + 8) * 2;       // 272
    constexpr int XSZ = 128 * RS;           // 34816
    constexpr int WOFF = 2 * XSZ;           // 69632
    constexpr int WSZ = 128 * RS;           // 34816
    constexpr int BOFF = WOFF + WSZ;        // 104448

    extern __shared__ char sm[];
    uint32_t sb = smem_u32(sm);
    uint32_t xh = sb, xl = sb + XSZ, wh = sb + WOFF;
    float* b1s = (float*)(sm + BOFF);
    float* b2s = b1s + 128;

    const int tid = threadIdx.x;
    const int wid = tid >> 5, lane = tid & 31;
    const int wm = wid >> 1, wn = wid & 1;
    const int n0 = blockIdx.x * 128;
    const float eps2 = 1e-16f * __expf(8.f * g_maxoff);

    // gather cat rows: msg half (compute log + split), ns half (uint4 copies)
    for (int e = tid; e < 128 * 16; e += 256) {
        int t = e >> 4, q = e & 15;
        int col = q * 4;
        long long n = n0 + t;
        if (n >= NNODES) n = NNODES - 1;    // clamp (tail rows unused)
        float4 s = *(const float4*)(g_expsum + n * 64 + col);
        float4 v = make_float4(0.125f * __logf(eps2 + s.x), 0.125f * __logf(eps2 + s.y),
                               0.125f * __logf(eps2 + s.z), 0.125f * __logf(eps2 + s.w));
        uint32_t h0, l0, h1, l1;
        split_pair_h(v.x, v.y, h0, l0);
        split_pair_h(v.z, v.w, h1, l1);
        int byte = t * RS + col * 2;
        *(uint32_t*)(sm + byte) = h0;
        *(uint32_t*)(sm + byte + 4) = h1;
        *(uint32_t*)(sm + XSZ + byte) = l0;
        *(uint32_t*)(sm + XSZ + byte + 4) = l1;
    }
    for (int e = tid; e < 128 * 8; e += 256) {
        int t = e >> 3, fq = e & 7;
        long long n = n0 + t;
        if (n >= NNODES) n = NNODES - 1;
        long long base = n * 64 + fq * 8;
        int byte = t * RS + (64 + fq * 8) * 2;
        *(uint4*)(sm + byte) = *(const uint4*)(g_nsh_hi + base);
        *(uint4*)(sm + XSZ + byte) = *(const uint4*)(g_nsh_lo + base);
    }
    copy_w_smem(sm, WOFF, w1o, 128, 128, RS, tid);
    if (tid < 128) b1s[tid] = b1[tid];
    if (tid < 64) b2s[tid] = b2[tid];
    __syncthreads();

    float c[64];
    // layer 1: N=128, warp half = 64 -> NT8=8
    warp_gemm32<128, 8>(xh, xl, wh, RS, RS, wm, wn, lane, c);
    __syncthreads();

#pragma unroll
    for (int h = 0; h < 2; h++) {
#pragma unroll
        for (int nt = 0; nt < 8; nt++) {
            int col = wn * 64 + nt * 8 + (lane & 3) * 2;
            float bb0 = b1s[col], bb1 = b1s[col + 1];
            int r0 = wm * 32 + h * 16 + (lane >> 2);
            const float* cc = c + h * 32 + nt * 4;
            float v0 = fmaxf(cc[0] + bb0, 0.f), v1 = fmaxf(cc[1] + bb1, 0.f);
            float v2 = fmaxf(cc[2] + bb0, 0.f), v3 = fmaxf(cc[3] + bb1, 0.f);
            uint32_t hw, lw;
            int byte0 = r0 * RS + col * 2;
            split_pair_h(v0, v1, hw, lw);
            *(uint32_t*)(sm + byte0) = hw;
            *(uint32_t*)(sm + XSZ + byte0) = lw;
            int byte1 = (r0 + 8) * RS + col * 2;
            split_pair_h(v2, v3, hw, lw);
            *(uint32_t*)(sm + byte1) = hw;
            *(uint32_t*)(sm + XSZ + byte1) = lw;
        }
    }
    copy_w_smem(sm, WOFF, w2o, 64, 128, RS, tid);
    __syncthreads();

    // layer 2: N=64, warp half = 32 -> NT8=4
    warp_gemm32<128, 4>(xh, xl, wh, RS, RS, wm, wn, lane, c);

    // epilogue 2: direct f32x2 stores
#pragma unroll
    for (int h = 0; h < 2; h++) {
#pragma unroll
        for (int nt = 0; nt < 4; nt++) {
            int col = wn * 32 + nt * 8 + (lane & 3) * 2;
            float bb0 = b2s[col], bb1 = b2s[col + 1];
            int r0 = wm * 32 + h * 16 + (lane >> 2);
            const float* cc = c + h * 16 + nt * 4;
            long long na = n0 + r0, nb = n0 + r0 + 8;
            if (na < NNODES) {
                float2 v = make_float2(cc[0] + bb0, cc[1] + bb1);
                *(float2*)(out + na * 64 + col) = v;
            }
            if (nb < NNODES) {
                float2 v = make_float2(cc[2] + bb0, cc[3] + bb1);
                *(float2*)(out + nb * 64 + col) = v;
            }
        }
    }
}

// ---------------------------------------------------------------------------
extern "C" void kernel_launch(void* const* d_in, const int* in_sizes, int n_in,
                              void* d_out, int out_size) {
    const float* ns   = (const float*)d_in[0];
    const int*   idx0 = (const int*)d_in[1];
    const int*   idx1 = (const int*)d_in[2];
    const int*   idx2 = (const int*)d_in[3];
    const float* r0w1 = (const float*)d_in[4];
    const float* r0b1 = (const float*)d_in[5];
    const float* r0w2 = (const float*)d_in[6];
    const float* r0b2 = (const float*)d_in[7];
    const float* r1w1 = (const float*)d_in[8];
    const float* r1b1 = (const float*)d_in[9];
    const float* r1w2 = (const float*)d_in[10];
    const float* r1b2 = (const float*)d_in[11];
    const float* r2w1 = (const float*)d_in[12];
    const float* r2b1 = (const float*)d_in[13];
    const float* r2w2 = (const float*)d_in[14];
    const float* r2b2 = (const float*)d_in[15];
    const float* uw1  = (const float*)d_in[16];
    const float* ub1  = (const float*)d_in[17];
    const float* uw2  = (const float*)d_in[18];
    const float* ub2  = (const float*)d_in[19];
    float* out = (float*)d_out;

    const int T01 = 300000, T2 = 200000;

    // weight offsets in g_wh (elements)
    const long long O_R0W1 = 0, O_R0W2 = 16384, O_R1W1 = 32768, O_R1W2 = 49152;
    const long long O_R2W1 = 65536, O_R2W2 = 102400, O_UW1 = 139264, O_UW2 = 155648;

    const int SMA2 = 2 * (128 * 272) + 128 * 272 + 2 * 128 * 4 + 64;   // 105.5KB
    const int SMA3 = 2 * (128 * 400) + 192 * 400 + 2 * 192 * 4 + 64;   // 180.8KB
    const int SMU  = 2 * (128 * 272) + 128 * 272 + 128 * 4 + 64 * 4 + 64;
    cudaFuncSetAttribute((const void*)k_rel_mma<2, 2>, cudaFuncAttributeMaxDynamicSharedMemorySize, SMA2);
    cudaFuncSetAttribute((const void*)k_rel_mma<3, 1>, cudaFuncAttributeMaxDynamicSharedMemorySize, SMA3);
    cudaFuncSetAttribute((const void*)k_update_mma, cudaFuncAttributeMaxDynamicSharedMemorySize, SMU);

    // K0: fused prep (expsum init + ns hi/lo split + weight fp16)
    {
        long long n4 = (long long)NNODES * 64 / 4;   // 3.2M
        k_prep<<<(int)((n4 + 255) / 256), 256>>>(ns, r0w1, r0w2, r1w1, r1w2,
                                                 r2w1, r2w2, uw1, uw2);
    }

    // K1..K3 (fused MLP + scatter)
    k_rel_mma<2, 2><<<(T01 + 127) / 128, 256, SMA2>>>(idx0, O_R0W1, r0b1, O_R0W2, r0b2, T01);
    k_rel_mma<2, 2><<<(T01 + 127) / 128, 256, SMA2>>>(idx1, O_R1W1, r1b1, O_R1W2, r1b2, T01);
    k_rel_mma<3, 1><<<(T2 + 127) / 128, 256, SMA3>>>(idx2, O_R2W1, r2b1, O_R2W2, r2b2, T2);

    // K4
    k_update_mma<<<(NNODES + 127) / 128, 256, SMU>>>(O_UW1, ub1, O_UW2, ub2, out);
}